// round 1
// baseline (speedup 1.0000x reference)
#include <cuda_runtime.h>
#include <cuda_bf16.h>
#include <math.h>

// ---------------- problem constants (from setup_inputs) ----------------
#define MAX_K     16384
#define MAX_N     4096
#define MAX_B     16

#define PI_F        3.14159265358979323846f
#define INV2PI_F    0.15915494309189535f     // 1/(2*pi)
#define TWOPI_HI    6.2831854820251465f      // float(2*pi)
#define TWOPI_LO   -1.7484556000423536e-7f   // 2*pi - TWOPI_HI (as float)
#define MAGIC_RND   12582912.0f              // 1.5 * 2^23 (round-to-nearest trick)
#define INV_SQRT_2PI 0.3989422804014327f

// ---------------- device scratch (no allocations allowed) ----------------
__device__ float4 g_packed[MAX_N];     // {px, py, pz, q}
__device__ float  g_perk[MAX_K];       // folded per-k energy contribution
__device__ int    g_noff[MAX_B + 1];   // node segment offsets
__device__ int    g_koff[MAX_B + 1];   // k segment offsets

__device__ __forceinline__ int lower_bound_i(const int* a, int n, int v) {
    int lo = 0, hi = n;
    while (lo < hi) {
        int m = (lo + hi) >> 1;
        if (a[m] < v) lo = m + 1; else hi = m;
    }
    return lo;
}

// ---------------- kernel 1: pack node data + segment offsets -------------
__global__ void pack_kernel(const float* __restrict__ node_pos,
                            const float* __restrict__ q,
                            const int*   __restrict__ batch,
                            const int*   __restrict__ kbatch,
                            int N, int K, int B)
{
    int i = blockIdx.x * blockDim.x + threadIdx.x;
    if (i < N) {
        float4 p;
        p.x = node_pos[3 * i + 0];
        p.y = node_pos[3 * i + 1];
        p.z = node_pos[3 * i + 2];
        p.w = q[i];
        g_packed[i] = p;
    }
    if (blockIdx.x == 0) {
        int t = threadIdx.x;
        if (t <= B)              g_noff[t]         = lower_bound_i(batch,  N, t);
        else if (t <= 2 * B + 1) g_koff[t - B - 1] = lower_bound_i(kbatch, K, t - B - 1);
    }
}

// ---------------- kernel 2: per-k structure factors ----------------------
// One warp per k vector. Lanes stride the node segment of k's graph.
__global__ void __launch_bounds__(256)
perk_kernel(const float* __restrict__ kvec,
            const float* __restrict__ knorm2,
            const int*   __restrict__ kbatch,
            const float* __restrict__ k0mask,
            const float* __restrict__ volume,
            int K)
{
    int warp = (blockIdx.x * blockDim.x + threadIdx.x) >> 5;
    int lane = threadIdx.x & 31;
    if (warp >= K) return;
    int k = warp;

    int b  = kbatch[k];
    float kx = kvec[3 * k + 0];
    float ky = kvec[3 * k + 1];
    float kz = kvec[3 * k + 2];
    int ns = g_noff[b];
    int ne = g_noff[b + 1];

    float sc = 0.0f, ss = 0.0f;
    for (int n = ns + lane; n < ne; n += 32) {
        float4 pq = g_packed[n];
        float x = kx * pq.x;
        x = fmaf(ky, pq.y, x);
        x = fmaf(kz, pq.z, x);
        // Cody-Waite range reduction to [-pi, pi] so MUFU sin/cos stays accurate
        float t    = fmaf(x, INV2PI_F, MAGIC_RND);
        float nrot = t - MAGIC_RND;
        float r    = fmaf(nrot, -TWOPI_HI, x);
        r          = fmaf(nrot, -TWOPI_LO, r);
        float s, c;
        __sincosf(r, &s, &c);
        sc = fmaf(pq.w, c, sc);
        ss = fmaf(pq.w, s, ss);
    }
    // warp reduction (fixed order -> deterministic)
    #pragma unroll
    for (int o = 16; o; o >>= 1) {
        sc += __shfl_xor_sync(0xFFFFFFFFu, sc, o);
        ss += __shfl_xor_sync(0xFFFFFFFFu, ss, o);
    }
    if (lane == 0) {
        float kn = knorm2[k];
        float fs = __expf(-0.5f * kn);               // SIGMA = 1
        float kf = (k0mask[k] > 0.0f) ? 0.0f : (1.0f / kn);
        // folded: 0.5*vol*per_k/(2pi)^6 with pref = fs*(2pi)^3/vol
        float w = 4.0f * PI_F * fs * fs * kf / volume[b];
        g_perk[k] = w * (sc * sc + ss * ss);
    }
}

// ---------------- kernel 3: deterministic per-graph reduction ------------
__global__ void __launch_bounds__(256)
finalize_kernel(float* __restrict__ out)
{
    int b   = blockIdx.x;
    int tid = threadIdx.x;

    float acc = 0.0f;
    int ks = g_koff[b], ke = g_koff[b + 1];
    for (int k = ks + tid; k < ke; k += 256) acc += g_perk[k];

    float self = 0.0f;
    int ns = g_noff[b], ne = g_noff[b + 1];
    for (int n = ns + tid; n < ne; n += 256) {
        float q = g_packed[n].w;
        self = fmaf(q, q, self);
    }

    __shared__ float sA[256], sB[256];
    sA[tid] = acc; sB[tid] = self;
    __syncthreads();
    #pragma unroll
    for (int s = 128; s > 0; s >>= 1) {
        if (tid < s) { sA[tid] += sA[tid + s]; sB[tid] += sB[tid + s]; }
        __syncthreads();
    }
    if (tid == 0) {
        out[b] = sA[0] - 0.5f * sB[0] * INV_SQRT_2PI;
    }
}

// ---------------- launch ---------------------------------------------------
extern "C" void kernel_launch(void* const* d_in, const int* in_sizes, int n_in,
                              void* d_out, int out_size)
{
    const float* k_vectors   = (const float*)d_in[0];
    const float* k_norm2     = (const float*)d_in[1];
    const int*   kbatch      = (const int*)  d_in[2];
    const float* k0_mask     = (const float*)d_in[3];
    const float* source_feat = (const float*)d_in[4];
    const float* node_pos    = (const float*)d_in[5];
    const int*   batch       = (const int*)  d_in[6];
    const float* volume      = (const float*)d_in[7];
    // d_in[8] = pbc, unused

    int K = in_sizes[2];
    int N = in_sizes[6];
    int B = in_sizes[7];
    if (K > MAX_K) K = MAX_K;
    if (N > MAX_N) N = MAX_N;
    if (B > MAX_B) B = MAX_B;

    float* out = (float*)d_out;

    int packBlocks = (N + 255) / 256;
    pack_kernel<<<packBlocks, 256>>>(node_pos, source_feat, batch, kbatch, N, K, B);

    int warpsPerBlock = 8; // 256 threads
    int perkBlocks = (K + warpsPerBlock - 1) / warpsPerBlock;
    perk_kernel<<<perkBlocks, 256>>>(k_vectors, k_norm2, kbatch, k0_mask, volume, K);

    finalize_kernel<<<B, 256>>>(out);
}

// round 2
// speedup vs baseline: 1.0122x; 1.0122x over previous
#include <cuda_runtime.h>
#include <cuda_bf16.h>
#include <math.h>

// ---------------- problem constants (from setup_inputs) ----------------
#define MAX_K     16384
#define MAX_B     16

#define PI_F        3.14159265358979323846f
#define INV2PI_F    0.15915494309189535f     // 1/(2*pi)
#define TWOPI_HI    6.2831854820251465f      // float(2*pi)
#define TWOPI_LO   -1.7484556000423536e-7f   // 2*pi - TWOPI_HI
#define MAGIC_RND   12582912.0f              // 1.5 * 2^23 round-to-nearest trick
#define INV_SQRT_2PI 0.3989422804014327f

#define SMEM_NODES  1536                     // float4 budget (24 KB)

// per-k folded energy contribution scratch
__device__ float g_perk[MAX_K];

__device__ __forceinline__ int lower_bound_i(const int* __restrict__ a, int n, int v) {
    int lo = 0, hi = n;
    while (lo < hi) {
        int m = (lo + hi) >> 1;
        if (__ldg(a + m) < v) lo = m + 1; else hi = m;
    }
    return lo;
}

// Cody-Waite reduce to [-pi,pi], then fast sincos
__device__ __forceinline__ void fast_sincos_cw(float x, float* s, float* c) {
    float t    = fmaf(x, INV2PI_F, MAGIC_RND);
    float nrot = t - MAGIC_RND;
    float r    = fmaf(nrot, -TWOPI_HI, x);
    r          = fmaf(nrot, -TWOPI_LO, r);
    __sincosf(r, s, c);
}

// ---------------- kernel 1: per-k structure factors (fused pack) ---------
// 8 warps per block, one warp per k. Block cooperatively stages its node
// range (contiguous because batch & kbatch are both sorted) into smem.
__global__ void __launch_bounds__(256)
perk_kernel(const float* __restrict__ kvec,
            const float* __restrict__ knorm2,
            const int*   __restrict__ kbatch,
            const float* __restrict__ k0mask,
            const float* __restrict__ volume,
            const float* __restrict__ node_pos,
            const float* __restrict__ q,
            const int*   __restrict__ batch,
            int N, int K, int B)
{
    __shared__ float4 s_nodes[SMEM_NODES];
    __shared__ int    s_noff[MAX_B + 1];

    int tid  = threadIdx.x;
    int wid  = tid >> 5;
    int lane = tid & 31;

    // segment offsets (17 cheap binary searches)
    if (tid <= B) s_noff[tid] = lower_bound_i(batch, N, tid);
    __syncthreads();

    int k0    = blockIdx.x * 8;
    int kLast = min(k0 + 7, K - 1);
    int b0 = kbatch[k0];
    int b1 = kbatch[kLast];

    int ns  = s_noff[b0];
    int ne  = s_noff[b1 + 1];
    int cnt = ne - ns;
    bool use_smem = (cnt <= SMEM_NODES);

    if (use_smem) {
        for (int i = tid; i < cnt; i += 256) {
            int n = ns + i;
            float4 p;
            p.x = __ldg(node_pos + 3 * n + 0);
            p.y = __ldg(node_pos + 3 * n + 1);
            p.z = __ldg(node_pos + 3 * n + 2);
            p.w = __ldg(q + n);
            s_nodes[i] = p;
        }
    }
    __syncthreads();

    int k = k0 + wid;
    if (k >= K) return;

    int b = kbatch[k];
    float kx = kvec[3 * k + 0];
    float ky = kvec[3 * k + 1];
    float kz = kvec[3 * k + 2];

    float sc = 0.0f, ss = 0.0f;

    if (use_smem) {
        int ws = s_noff[b] - ns;
        int we = s_noff[b + 1] - ns;
        #pragma unroll 2
        for (int n = ws + lane; n < we; n += 32) {
            float4 pq = s_nodes[n];
            float x = kx * pq.x;
            x = fmaf(ky, pq.y, x);
            x = fmaf(kz, pq.z, x);
            float s, c;
            fast_sincos_cw(x, &s, &c);
            sc = fmaf(pq.w, c, sc);
            ss = fmaf(pq.w, s, ss);
        }
    } else {
        // fallback: direct global loads (correctness path)
        int ws = s_noff[b];
        int we = s_noff[b + 1];
        for (int n = ws + lane; n < we; n += 32) {
            float px = __ldg(node_pos + 3 * n + 0);
            float py = __ldg(node_pos + 3 * n + 1);
            float pz = __ldg(node_pos + 3 * n + 2);
            float qw = __ldg(q + n);
            float x = kx * px;
            x = fmaf(ky, py, x);
            x = fmaf(kz, pz, x);
            float s, c;
            fast_sincos_cw(x, &s, &c);
            sc = fmaf(qw, c, sc);
            ss = fmaf(qw, s, ss);
        }
    }

    // fixed-order warp reduction -> deterministic
    #pragma unroll
    for (int o = 16; o; o >>= 1) {
        sc += __shfl_xor_sync(0xFFFFFFFFu, sc, o);
        ss += __shfl_xor_sync(0xFFFFFFFFu, ss, o);
    }
    if (lane == 0) {
        float kn = knorm2[k];
        float fs = __expf(-0.5f * kn);               // SIGMA = 1
        float kf = (k0mask[k] > 0.0f) ? 0.0f : (1.0f / kn);
        // folded: 0.5*vol*per_k/(2pi)^6 with pref = fs*(2pi)^3/vol
        float w = 4.0f * PI_F * fs * fs * kf / volume[b];
        g_perk[k] = w * (sc * sc + ss * ss);
    }
}

// ---------------- kernel 2: deterministic per-graph reduction ------------
__global__ void __launch_bounds__(256)
finalize_kernel(const int*   __restrict__ kbatch,
                const int*   __restrict__ batch,
                const float* __restrict__ q,
                float* __restrict__ out,
                int N, int K, int B)
{
    int b   = blockIdx.x;
    int tid = threadIdx.x;

    __shared__ int s_off[4];
    if (tid < 2)      s_off[tid]     = lower_bound_i(kbatch, K, b + tid);
    else if (tid < 4) s_off[tid]     = lower_bound_i(batch,  N, b + tid - 2);
    __syncthreads();

    int ks = s_off[0], ke = s_off[1];
    int ns = s_off[2], ne = s_off[3];

    float acc = 0.0f;
    for (int k = ks + tid; k < ke; k += 256) acc += g_perk[k];

    float self = 0.0f;
    for (int n = ns + tid; n < ne; n += 256) {
        float qv = __ldg(q + n);
        self = fmaf(qv, qv, self);
    }

    __shared__ float sA[256], sB[256];
    sA[tid] = acc; sB[tid] = self;
    __syncthreads();
    #pragma unroll
    for (int s = 128; s > 0; s >>= 1) {
        if (tid < s) { sA[tid] += sA[tid + s]; sB[tid] += sB[tid + s]; }
        __syncthreads();
    }
    if (tid == 0) {
        out[b] = sA[0] - 0.5f * sB[0] * INV_SQRT_2PI;
    }
}

// ---------------- launch ---------------------------------------------------
extern "C" void kernel_launch(void* const* d_in, const int* in_sizes, int n_in,
                              void* d_out, int out_size)
{
    const float* k_vectors   = (const float*)d_in[0];
    const float* k_norm2     = (const float*)d_in[1];
    const int*   kbatch      = (const int*)  d_in[2];
    const float* k0_mask     = (const float*)d_in[3];
    const float* source_feat = (const float*)d_in[4];
    const float* node_pos    = (const float*)d_in[5];
    const int*   batch       = (const int*)  d_in[6];
    const float* volume      = (const float*)d_in[7];
    // d_in[8] = pbc, unused

    int K = in_sizes[2];
    int N = in_sizes[6];
    int B = in_sizes[7];
    if (K > MAX_K) K = MAX_K;
    if (B > MAX_B) B = MAX_B;

    float* out = (float*)d_out;

    int perkBlocks = (K + 7) / 8;
    perk_kernel<<<perkBlocks, 256>>>(k_vectors, k_norm2, kbatch, k0_mask,
                                     volume, node_pos, source_feat, batch,
                                     N, K, B);

    finalize_kernel<<<B, 256>>>(kbatch, batch, source_feat, out, N, K, B);
}